// round 5
// baseline (speedup 1.0000x reference)
#include <cuda_runtime.h>
#include <cstddef>

// STPCell fused kernel, R3: batch-split grid (4096 CTAs = 1024 j x 4 b-groups),
// register accumulators (no in-loop reduction), 2-deep X/U prefetch, streaming
// loads (__ldcs) for the 268 MB of single-use X/U data.

#define HH   1024
#define IND  512
#define BB   32
#define BPC  8          // batches per CTA
#define BSPL 4          // b-groups per j

__device__ __forceinline__ float sigf(float v) {
    return 1.0f / (1.0f + __expf(-v));
}

__global__ __launch_bounds__(256, 3) void stp_main(
    const float* __restrict__ x_in,   // (IN, B)
    const float* __restrict__ h,      // (B, H)
    const float* __restrict__ X,      // (B, H, H)
    const float* __restrict__ U,      // (B, H, H)
    const float* __restrict__ c_x,    // (H, H)
    const float* __restrict__ c_u,    // (H, H)
    const float* __restrict__ c_U,    // (H, H)
    const float* __restrict__ c_h,    // (H, 1)
    const float* __restrict__ w,      // (H, H)
    const float* __restrict__ p,      // (H, IN)
    const float* __restrict__ bias,   // (H, 1)
    float* __restrict__ out)          // (B, H)
{
    const int j     = blockIdx.x >> 2;          // adjacent CTAs share j (L2 reuse)
    const int bbase = (blockIdx.x & 3) * BPC;   // this CTA's batch range
    const int tid   = threadIdx.x;
    const int lane  = tid & 31;
    const int warp  = tid >> 5;
    const int rowP  = j * (HH / 4) + tid;       // float4 idx of (j, 4t..4t+3)

    const float4* __restrict__ X4 = reinterpret_cast<const float4*>(X);
    const float4* __restrict__ U4 = reinterpret_cast<const float4*>(U);
    const float4* __restrict__ h4 = reinterpret_cast<const float4*>(h);

    __shared__ float sbuf[32][BPC];   // px partial sums
    __shared__ float sred[8][BPC];    // epilogue warp partials
    __shared__ float px_s[BPC];
    __shared__ float hj_s[BPC];

    // ---- prologue loads (all issued before px compute) ----
    const float4 cxv = reinterpret_cast<const float4*>(c_x)[rowP];
    const float4 cuv = reinterpret_cast<const float4*>(c_u)[rowP];
    const float4 cUv = reinterpret_cast<const float4*>(c_U)[rowP];
    const float4 wv  = reinterpret_cast<const float4*>(w)[rowP];

    #define ROW4(b) (((b) * HH + j) * (HH / 4) + tid)
    float4 xv0 = __ldcs(X4 + ROW4(bbase + 0));
    float4 uv0 = __ldcs(U4 + ROW4(bbase + 0));
    float4 xv1 = __ldcs(X4 + ROW4(bbase + 1));
    float4 uv1 = __ldcs(U4 + ROW4(bbase + 1));
    float4 hv  = h4[(bbase + 0) * (HH / 4) + tid];

    if (tid < BPC) hj_s[tid] = h[(bbase + tid) * HH + j];

    // ---- (p @ x)[j, bbase..bbase+7]: 32 segments of 16 i, b = tid&7 ----
    {
        const int seg = tid >> 3;
        const int bl  = tid & 7;
        const float* prow = p + j * IND;
        float a = 0.0f;
        #pragma unroll 8
        for (int i = seg * 16; i < seg * 16 + 16; ++i)
            a = fmaf(prow[i], x_in[i * BB + (bbase + bl)], a);
        sbuf[seg][bl] = a;
    }
    __syncthreads();
    if (tid < BPC) {
        float s = 0.0f;
        #pragma unroll
        for (int q = 0; q < 32; ++q) s += sbuf[q][tid];
        px_s[tid] = s;
    }
    __syncthreads();

    // ---- per-(j,k) sigmoid constants, once, in registers ----
    float4 zx, zu, uc;
    zx.x = 0.001f + 0.099f * sigf(cxv.x);
    zx.y = 0.001f + 0.099f * sigf(cxv.y);
    zx.z = 0.001f + 0.099f * sigf(cxv.z);
    zx.w = 0.001f + 0.099f * sigf(cxv.w);
    zu.x = 0.001f + 0.099f * sigf(cuv.x);
    zu.y = 0.001f + 0.099f * sigf(cuv.y);
    zu.z = 0.001f + 0.099f * sigf(cuv.z);
    zu.w = 0.001f + 0.099f * sigf(cuv.w);
    uc.x = 0.9f * sigf(cUv.x);
    uc.y = 0.9f * sigf(cUv.y);
    uc.z = 0.9f * sigf(cUv.z);
    uc.w = 0.9f * sigf(cUv.w);

    // ---- streaming loop: 8 batches, 2-deep X/U pipeline, reg accumulators ----
    float acc[BPC];
    #pragma unroll
    for (int i = 0; i < BPC; ++i) acc[i] = 0.0f;

    #pragma unroll
    for (int ib = 0; ib < BPC; ++ib) {
        const int ip2 = (ib + 2 < BPC) ? ib + 2 : BPC - 1;
        const int ip1 = (ib + 1 < BPC) ? ib + 1 : BPC - 1;
        float4 xn = __ldcs(X4 + ROW4(bbase + ip2));
        float4 un = __ldcs(U4 + ROW4(bbase + ip2));
        float4 hn = h4[(bbase + ip1) * (HH / 4) + tid];

        const float hj = hj_s[ib];

        // X_new = fma(z_x, 1-X, X) - U*(X*hj)
        // U_new = Ucap*(z_u+hj) + U*((1-z_u) - Ucap*hj), clipped [Ucap, 1]
        // acc  += (w * U_new * X_new) * h[b,k]
        #define STP_PROC(C)                                                 \
        {                                                                   \
            float xx = xv0.C, uu = uv0.C;                                   \
            float xnew = fmaf(zx.C, 1.0f - xx, xx);                         \
            xnew = fmaf(-uu, xx * hj, xnew);                                \
            float addu = uc.C * (zu.C + hj);                                \
            float cofu = fmaf(-uc.C, hj, 1.0f - zu.C);                      \
            float unew = fmaf(uu, cofu, addu);                              \
            unew = fminf(fmaxf(unew, uc.C), 1.0f);                         \
            acc[ib] = fmaf(wv.C * unew * xnew, hv.C, acc[ib]);              \
        }
        STP_PROC(x) STP_PROC(y) STP_PROC(z) STP_PROC(w)
        #undef STP_PROC

        xv0 = xv1; uv0 = uv1;
        xv1 = xn;  uv1 = un;
        hv  = hn;
    }
    #undef ROW4

    // ---- epilogue: reduce 8 accumulators (independent shuffle trees) ----
    #pragma unroll
    for (int i = 0; i < BPC; ++i) {
        float v = acc[i];
        #pragma unroll
        for (int o = 16; o > 0; o >>= 1)
            v += __shfl_xor_sync(0xffffffffu, v, o);
        if (lane == 0) sred[warp][i] = v;
    }
    __syncthreads();

    if (tid < BPC) {
        const int b = bbase + tid;
        float rec = 0.0f;
        #pragma unroll
        for (int q = 0; q < 8; ++q) rec += sred[q][tid];

        float pre = rec + px_s[tid] + bias[j];
        float zh  = 0.5f * sigf(c_h[j]);          // E_H = 0.5
        float hbj = hj_s[tid];                    // == h[b*HH + j]
        out[b * HH + j] = fmaf(zh, sigf(pre) - hbj, hbj);
    }
}

// ---------------------------------------------------------------------------
// Inputs (metadata order): x, h, X, U, c_x, c_u, c_U, c_h, w, p, b
// ---------------------------------------------------------------------------
extern "C" void kernel_launch(void* const* d_in, const int* in_sizes, int n_in,
                              void* d_out, int out_size)
{
    const float* x_in = (const float*)d_in[0];
    const float* h    = (const float*)d_in[1];
    const float* X    = (const float*)d_in[2];
    const float* U    = (const float*)d_in[3];
    const float* c_x  = (const float*)d_in[4];
    const float* c_u  = (const float*)d_in[5];
    const float* c_U  = (const float*)d_in[6];
    const float* c_h  = (const float*)d_in[7];
    const float* w    = (const float*)d_in[8];
    const float* p    = (const float*)d_in[9];
    const float* bias = (const float*)d_in[10];
    float* out = (float*)d_out;

    stp_main<<<HH * BSPL, 256>>>(x_in, h, X, U, c_x, c_u, c_U, c_h, w, p, bias, out);
}

// round 6
// speedup vs baseline: 1.4145x; 1.4145x over previous
#include <cuda_runtime.h>
#include <cstddef>

// STPCell fused kernel, R5: R3 skeleton (one CTA per j, all 32 batches),
// plus 4-batch register accumulator groups (shuffle tree amortized 4x),
// 2-deep X/U/h software pipeline with strength-reduced pointers, and
// streaming (__ldcs) loads for the single-use X/U data.

#define HH   1024
#define IND  512
#define BB   32
#define S4   (HH * HH / 4)      // float4 stride between batches of X/U

__device__ __forceinline__ float sigf(float v) {
    return 1.0f / (1.0f + __expf(-v));
}

__global__ __launch_bounds__(256, 3) void stp_main(
    const float* __restrict__ x_in,   // (IN, B)
    const float* __restrict__ h,      // (B, H)
    const float* __restrict__ X,      // (B, H, H)
    const float* __restrict__ U,      // (B, H, H)
    const float* __restrict__ c_x,    // (H, H)
    const float* __restrict__ c_u,    // (H, H)
    const float* __restrict__ c_U,    // (H, H)
    const float* __restrict__ c_h,    // (H, 1)
    const float* __restrict__ w,      // (H, H)
    const float* __restrict__ p,      // (H, IN)
    const float* __restrict__ bias,   // (H, 1)
    float* __restrict__ out)          // (B, H)
{
    const int j    = blockIdx.x;
    const int tid  = threadIdx.x;
    const int lane = tid & 31;
    const int warp = tid >> 5;
    const int rowP = j * (HH / 4) + tid;     // float4 idx of (j, 4t..4t+3)

    const float4* __restrict__ X4 = reinterpret_cast<const float4*>(X);
    const float4* __restrict__ U4 = reinterpret_cast<const float4*>(U);
    const float4* __restrict__ h4 = reinterpret_cast<const float4*>(h);

    __shared__ float sred[8][BB];    // px partials, then epilogue partials
    __shared__ float px_s[BB];
    __shared__ float hj_s[BB];

    // ---- prologue constant loads (issued before px compute) ----
    const float4 cxv = reinterpret_cast<const float4*>(c_x)[rowP];
    const float4 cuv = reinterpret_cast<const float4*>(c_u)[rowP];
    const float4 cUv = reinterpret_cast<const float4*>(c_U)[rowP];
    const float4 wv  = reinterpret_cast<const float4*>(w)[rowP];

    // ---- streaming pointers + 2-deep pipeline fill (batches 0 and 1) ----
    const float4* Xp = X4 + rowP;
    const float4* Up = U4 + rowP;
    const float4* hp = h4 + tid;

    float4 x0 = __ldcs(Xp); Xp += S4;
    float4 u0 = __ldcs(Up); Up += S4;
    float4 x1 = __ldcs(Xp); Xp += S4;     // Xp/Up now at batch 2
    float4 u1 = __ldcs(Up); Up += S4;
    float4 h0 = hp[0]; hp += HH / 4;
    float4 h1 = hp[0]; hp += HH / 4;      // hp now at batch 2

    if (tid < BB) hj_s[tid] = h[tid * HH + j];

    // ---- (p @ x)[j, 0..31]: 8 segments of 64 i, b = lane ----
    {
        const int b   = tid & 31;
        const int seg = tid >> 5;
        const float* prow = p + j * IND;
        float a = 0.0f;
        #pragma unroll 8
        for (int i = seg * 64; i < seg * 64 + 64; ++i)
            a = fmaf(prow[i], x_in[i * BB + b], a);
        sred[seg][b] = a;
    }
    __syncthreads();
    if (tid < BB) {
        float s = 0.0f;
        #pragma unroll
        for (int q = 0; q < 8; ++q) s += sred[q][tid];
        px_s[tid] = s;
    }
    __syncthreads();            // sred free for epilogue partials

    // ---- per-(j,k) sigmoid constants, once, in registers ----
    float4 zx, zu, uc;
    zx.x = 0.001f + 0.099f * sigf(cxv.x);
    zx.y = 0.001f + 0.099f * sigf(cxv.y);
    zx.z = 0.001f + 0.099f * sigf(cxv.z);
    zx.w = 0.001f + 0.099f * sigf(cxv.w);
    zu.x = 0.001f + 0.099f * sigf(cuv.x);
    zu.y = 0.001f + 0.099f * sigf(cuv.y);
    zu.z = 0.001f + 0.099f * sigf(cuv.z);
    zu.w = 0.001f + 0.099f * sigf(cuv.w);
    uc.x = 0.9f * sigf(cUv.x);
    uc.y = 0.9f * sigf(cUv.y);
    uc.z = 0.9f * sigf(cUv.z);
    uc.w = 0.9f * sigf(cUv.w);

    // ---- streaming loop: 8 groups x 4 batches ----
    #pragma unroll 1
    for (int g = 0; g < 8; ++g) {
        float a[4] = {0.0f, 0.0f, 0.0f, 0.0f};

        #pragma unroll
        for (int q = 0; q < 4; ++q) {
            const int b = g * 4 + q;
            // prefetch batch b+2 (pointers already there; clamp at 31)
            float4 xn = __ldcs(Xp);
            float4 un = __ldcs(Up);
            float4 hn = hp[0];
            if (b + 3 < BB) { Xp += S4; Up += S4; hp += HH / 4; }

            const float hj = hj_s[b];

            // X_new = fma(z_x, 1-X, X) - U*(X*hj)
            // U_new = Ucap*(z_u+hj) + U*((1-z_u) - Ucap*hj), clip [Ucap,1]
            // a[q] += (w * U_new * X_new) * h[b,k]
            #define STP_PROC(C)                                             \
            {                                                               \
                float xx = x0.C, uu = u0.C;                                 \
                float xnew = fmaf(zx.C, 1.0f - xx, xx);                     \
                xnew = fmaf(-uu, xx * hj, xnew);                            \
                float addu = uc.C * (zu.C + hj);                            \
                float cofu = fmaf(-uc.C, hj, 1.0f - zu.C);                  \
                float unew = fmaf(uu, cofu, addu);                          \
                unew = fminf(fmaxf(unew, uc.C), 1.0f);                     \
                a[q] = fmaf(wv.C * unew * xnew, h0.C, a[q]);                \
            }
            STP_PROC(x) STP_PROC(y) STP_PROC(z) STP_PROC(w)
            #undef STP_PROC

            x0 = x1; u0 = u1; h0 = h1;
            x1 = xn; u1 = un; h1 = hn;
        }

        // 4 interleaved shuffle trees (independent chains overlap)
        #pragma unroll
        for (int o = 16; o > 0; o >>= 1) {
            a[0] += __shfl_xor_sync(0xffffffffu, a[0], o);
            a[1] += __shfl_xor_sync(0xffffffffu, a[1], o);
            a[2] += __shfl_xor_sync(0xffffffffu, a[2], o);
            a[3] += __shfl_xor_sync(0xffffffffu, a[3], o);
        }
        if (lane == 0) {
            sred[warp][g * 4 + 0] = a[0];
            sred[warp][g * 4 + 1] = a[1];
            sred[warp][g * 4 + 2] = a[2];
            sred[warp][g * 4 + 3] = a[3];
        }
    }
    __syncthreads();

    // ---- finalize: thread b (< 32) writes out[b, j] ----
    if (tid < BB) {
        const int b = tid;
        float rec = 0.0f;
        #pragma unroll
        for (int q = 0; q < 8; ++q) rec += sred[q][b];

        float pre = rec + px_s[b] + bias[j];
        float zh  = 0.5f * sigf(c_h[j]);          // E_H = 0.5
        float hbj = hj_s[b];                      // == h[b*HH + j]
        out[b * HH + j] = fmaf(zh, sigf(pre) - hbj, hbj);
    }
}

// ---------------------------------------------------------------------------
// Inputs (metadata order): x, h, X, U, c_x, c_u, c_U, c_h, w, p, b
// ---------------------------------------------------------------------------
extern "C" void kernel_launch(void* const* d_in, const int* in_sizes, int n_in,
                              void* d_out, int out_size)
{
    const float* x_in = (const float*)d_in[0];
    const float* h    = (const float*)d_in[1];
    const float* X    = (const float*)d_in[2];
    const float* U    = (const float*)d_in[3];
    const float* c_x  = (const float*)d_in[4];
    const float* c_u  = (const float*)d_in[5];
    const float* c_U  = (const float*)d_in[6];
    const float* c_h  = (const float*)d_in[7];
    const float* w    = (const float*)d_in[8];
    const float* p    = (const float*)d_in[9];
    const float* bias = (const float*)d_in[10];
    float* out = (float*)d_out;

    stp_main<<<HH, 256>>>(x_in, h, X, U, c_x, c_u, c_U, c_h, w, p, bias, out);
}